// round 14
// baseline (speedup 1.0000x reference)
#include <cuda_runtime.h>
#include <cuda_fp16.h>
#include <cstdint>
#include <math.h>

// ---------------------------------------------------------------------------
// GraphSAGE 2-layer, all-fp16 intermediates, f32 accum.
// CSR gather-mean (fp16 payload, 16B-lane loads) + FUSED fp16 mma GEMMs
// (h stays in SMEM). 2-way asymmetric split pipeline:
//   S0: zero+detect, hist, scan, fill, g_A, g_B, fused_B, gather_final
//   S1: prep (from capture root), fused_A (overlaps g_B)
// ---------------------------------------------------------------------------

#define N_MAX 100000
#define E_MAX 1600000

__device__ uint32_t g_meanw[(size_t)N_MAX * 64];   // mean1, fp16 pairs
__device__ uint32_t g_xhw  [(size_t)N_MAX * 64];   // fp16(x) pairs
__device__ uint32_t g_y2bw [(size_t)N_MAX * 32];   // y2 lo cols, fp16 pairs
__device__ float    g_y2hi [(size_t)N_MAX * 64];   // y2 hi cols, f32
__device__ uint32_t g_w1tw [128 * 128];            // [N=128][K=256] fp16 pairs
__device__ uint32_t g_w2tw [128 * 64];             // [N=128][K=128] fp16 pairs
__device__ int      g_cnt[N_MAX];
__device__ int      g_cur[N_MAX];
__device__ int      g_rowptr[N_MAX];
__device__ int      g_eidx[E_MAX];
__device__ int      g_total;
__device__ int      g_is64;

// ---------------- helpers ----------------
__device__ __forceinline__ float2 h2f2(uint32_t v) {
    __half2 h = *reinterpret_cast<__half2*>(&v);
    return __half22float2(h);
}
__device__ __forceinline__ uint32_t f2h2(float lo, float hi) {
    __half2 h = __floats2half2_rn(lo, hi);
    return *reinterpret_cast<uint32_t*>(&h);
}
__device__ __forceinline__ void mma_f16(float (&c)[4], const uint32_t (&a)[4],
                                        const uint32_t (&b)[2]) {
    asm volatile(
        "mma.sync.aligned.m16n8k16.row.col.f32.f16.f16.f32 "
        "{%0,%1,%2,%3}, {%4,%5,%6,%7}, {%8,%9}, {%0,%1,%2,%3};"
        : "+f"(c[0]), "+f"(c[1]), "+f"(c[2]), "+f"(c[3])
        : "r"(a[0]), "r"(a[1]), "r"(a[2]), "r"(a[3]), "r"(b[0]), "r"(b[1]));
}
__device__ __forceinline__ void acc_h8(float (&acc)[8], uint4 v) {
    float2 f0 = h2f2(v.x), f1 = h2f2(v.y);
    float2 f2 = h2f2(v.z), f3 = h2f2(v.w);
    acc[0] += f0.x; acc[1] += f0.y; acc[2] += f1.x; acc[3] += f1.y;
    acc[4] += f2.x; acc[5] += f2.y; acc[6] += f3.x; acc[7] += f3.y;
}
__device__ __forceinline__ uint32_t smem_u32(const void* p) {
    uint32_t a;
    asm("{ .reg .u64 t; cvta.to.shared.u64 t, %1; cvt.u32.u64 %0, t; }"
        : "=r"(a) : "l"(p));
    return a;
}
__device__ __forceinline__ void cp_async16(uint32_t smem, const void* g, int src_bytes) {
    asm volatile("cp.async.ca.shared.global [%0], [%1], 16, %2;"
                 :: "r"(smem), "l"(g), "r"(src_bytes) : "memory");
}
#define CP_COMMIT() asm volatile("cp.async.commit_group;" ::: "memory")
#define CP_WAIT0()  asm volatile("cp.async.wait_group 0;" ::: "memory")
#define CP_WAIT1()  asm volatile("cp.async.wait_group 1;" ::: "memory")

// ---------------- CSR build ----------------
__device__ __forceinline__ int edge_at(const void* ei, long long idx, int is64) {
    if (is64) return (int)((const long long*)ei)[idx];
    return ((const int*)ei)[idx];
}
__global__ void zero_detect_kernel(int* __restrict__ cnt, const int* __restrict__ ei, int n) {
    int i = blockIdx.x * blockDim.x + threadIdx.x;
    if (i < n) cnt[i] = 0;
    if (i == 0) {
        int nz = 0;
        for (int q = 1; q < 256; q += 2) nz += (ei[q] != 0);
        g_is64 = (nz == 0) ? 1 : 0;
        g_total = 0;
    }
}
__global__ void hist_kernel(const void* __restrict__ ei, int* __restrict__ cnt, int ne) {
    int i = blockIdx.x * blockDim.x + threadIdx.x;
    int is64 = g_is64;
    int i2 = i * 2;
    if (((ne & 1) == 0) && i2 + 1 < ne) {
        int d0, d1;
        if (is64) {
            longlong2 v = __ldg((const longlong2*)ei + (ne + i2) / 2);
            d0 = (int)v.x; d1 = (int)v.y;
        } else {
            int2 v = __ldg((const int2*)ei + (ne + i2) / 2);
            d0 = v.x; d1 = v.y;
        }
        atomicAdd(&cnt[d0], 1);
        atomicAdd(&cnt[d1], 1);
    } else {
        for (int q = 0; q < 2; q++)
            if (i2 + q < ne)
                atomicAdd(&cnt[edge_at(ei, (long long)ne + i2 + q, is64)], 1);
    }
}
__global__ void scan_kernel(const int* __restrict__ cnt, int* __restrict__ rowptr,
                            int* __restrict__ cur, int* __restrict__ total, int n) {
    __shared__ int wsum[16];
    __shared__ int base_s;
    int tid = threadIdx.x;                 // 512
    int i = blockIdx.x * 512 + tid;
    int v = (i < n) ? cnt[i] : 0;
    int lane = tid & 31, w = tid >> 5;
    int p = v;
#pragma unroll
    for (int off = 1; off < 32; off <<= 1) {
        int t = __shfl_up_sync(0xFFFFFFFFu, p, off);
        if (lane >= off) p += t;
    }
    if (lane == 31) wsum[w] = p;
    __syncthreads();
    if (w == 0) {
        int s = (lane < 16) ? wsum[lane] : 0;
#pragma unroll
        for (int off = 1; off < 16; off <<= 1) {
            int t = __shfl_up_sync(0xFFFFFFFFu, s, off);
            if (lane >= off) s += t;
        }
        if (lane < 16) wsum[lane] = s;
        if (lane == 15) base_s = atomicAdd(total, s);
    }
    __syncthreads();
    int woff = (w > 0) ? wsum[w - 1] : 0;
    int excl = base_s + woff + p - v;
    if (i < n) { rowptr[i] = excl; cur[i] = excl; }
}
__global__ void fill_kernel(const void* __restrict__ ei, int* __restrict__ cur,
                            int* __restrict__ eidx, int ne) {
    int i = blockIdx.x * blockDim.x + threadIdx.x;
    int is64 = g_is64;
    int i2 = i * 2;
    if (((ne & 1) == 0) && i2 + 1 < ne) {
        int s0, s1, d0, d1;
        if (is64) {
            longlong2 sv = __ldg((const longlong2*)ei + i2 / 2);
            longlong2 dv = __ldg((const longlong2*)ei + (ne + i2) / 2);
            s0 = (int)sv.x; s1 = (int)sv.y;
            d0 = (int)dv.x; d1 = (int)dv.y;
        } else {
            int2 sv = __ldg((const int2*)ei + i2 / 2);
            int2 dv = __ldg((const int2*)ei + (ne + i2) / 2);
            s0 = sv.x; s1 = sv.y;
            d0 = dv.x; d1 = dv.y;
        }
        eidx[atomicAdd(&cur[d0], 1)] = s0;
        eidx[atomicAdd(&cur[d1], 1)] = s1;
    } else {
        for (int q = 0; q < 2; q++)
            if (i2 + q < ne) {
                int s = edge_at(ei, i2 + q, is64);
                int d = edge_at(ei, (long long)ne + i2 + q, is64);
                eidx[atomicAdd(&cur[d], 1)] = s;
            }
    }
}

// ---------------- prep: x->fp16, W transposes (fp16 pairs) ----------------
__global__ void prep_kernel(const float* __restrict__ x, uint32_t* __restrict__ xhw,
                            const float* __restrict__ Wl1, const float* __restrict__ Wr1,
                            uint32_t* __restrict__ W1tw,
                            const float* __restrict__ Wl2, const float* __restrict__ Wr2,
                            uint32_t* __restrict__ W2tw, int n32) {
    int i = blockIdx.x * blockDim.x + threadIdx.x;
    if (i < n32) {
        float4 v = __ldg((const float4*)x + i);
        uint2 o;
        o.x = f2h2(v.x, v.y);
        o.y = f2h2(v.z, v.w);
        *((uint2*)xhw + i) = o;
        return;
    }
    int j = i - n32;
    if (j < 128 * 128) {                       // W1tw: [nn][w], k = 2w,2w+1 over 256
        int nn = j >> 7, w = j & 127;
        int k0 = 2 * w;
        float v0, v1;
        if (k0 < 128) { v0 = Wl1[k0 * 128 + nn]; v1 = Wl1[(k0 + 1) * 128 + nn]; }
        else          { v0 = Wr1[(k0 - 128) * 128 + nn]; v1 = Wr1[(k0 - 127) * 128 + nn]; }
        W1tw[j] = f2h2(v0, v1);
    } else if (j < 128 * 128 + 128 * 64) {     // W2tw: [nn][w], k = 2w,2w+1 over 128
        int jj = j - 128 * 128;
        int nn = jj >> 6, w = jj & 63;
        int k0 = 2 * w;
        float v0, v1;
        if (nn < 64) { v0 = Wl2[k0 * 64 + nn];        v1 = Wl2[(k0 + 1) * 64 + nn]; }
        else         { v0 = Wr2[k0 * 64 + (nn - 64)]; v1 = Wr2[(k0 + 1) * 64 + (nn - 64)]; }
        W2tw[jj] = f2h2(v0, v1);
    }
}

// ---------------- wide gathers (range [base, nend)) ----------------
__global__ void gather_mean128_w(const uint32_t* __restrict__ featw,
                                 const int* __restrict__ rowptr,
                                 const int* __restrict__ cnt,
                                 const int* __restrict__ eidx,
                                 uint32_t* __restrict__ meanw, int base, int nend) {
    int gw   = (blockIdx.x * blockDim.x + threadIdx.x) >> 5;
    int lane = threadIdx.x & 31;
    int node = base + gw * 2 + (lane >> 4);
    int sl   = lane & 15;
    if (node >= nend) return;
    int beg = __ldg(&rowptr[node]);
    int deg = __ldg(&cnt[node]);
    int end = beg + deg;
    const uint4* fb = (const uint4*)featw;   // 16 uint4 per row
    float acc[8] = {0.f, 0.f, 0.f, 0.f, 0.f, 0.f, 0.f, 0.f};
    int j = beg;
    for (; j + 3 < end; j += 4) {
        int s0 = __ldg(&eidx[j]),     s1 = __ldg(&eidx[j + 1]);
        int s2 = __ldg(&eidx[j + 2]), s3 = __ldg(&eidx[j + 3]);
        uint4 v0 = __ldg(&fb[(size_t)s0 * 16 + sl]);
        uint4 v1 = __ldg(&fb[(size_t)s1 * 16 + sl]);
        uint4 v2 = __ldg(&fb[(size_t)s2 * 16 + sl]);
        uint4 v3 = __ldg(&fb[(size_t)s3 * 16 + sl]);
        acc_h8(acc, v0); acc_h8(acc, v1); acc_h8(acc, v2); acc_h8(acc, v3);
    }
    for (; j < end; ++j) {
        int s0 = __ldg(&eidx[j]);
        uint4 v0 = __ldg(&fb[(size_t)s0 * 16 + sl]);
        acc_h8(acc, v0);
    }
    float inv = 1.0f / fmaxf((float)deg, 1.0f);
    uint4 o;
    o.x = f2h2(acc[0] * inv, acc[1] * inv);
    o.y = f2h2(acc[2] * inv, acc[3] * inv);
    o.z = f2h2(acc[4] * inv, acc[5] * inv);
    o.w = f2h2(acc[6] * inv, acc[7] * inv);
    *(uint4*)(meanw + (size_t)node * 64 + sl * 4) = o;
}

// gather_final: quarter-warp per node, unroll-8 (deg~16 -> 2 iterations).
__global__ void gather_final64_w(const uint32_t* __restrict__ y2bw,
                                 const float* __restrict__ y2hi,
                                 const float* __restrict__ bl2,
                                 const int* __restrict__ rowptr,
                                 const int* __restrict__ cnt,
                                 const int* __restrict__ eidx,
                                 float* __restrict__ out, int n) {
    int gw   = (blockIdx.x * blockDim.x + threadIdx.x) >> 5;
    int lane = threadIdx.x & 31;
    int node = gw * 4 + (lane >> 3);
    int sl   = lane & 7;
    if (node >= n) return;
    int beg = __ldg(&rowptr[node]);
    int deg = __ldg(&cnt[node]);
    int end = beg + deg;
    const uint4* fb = (const uint4*)y2bw;    // 8 uint4 per row
    const int* ep = eidx;
    float acc[8] = {0.f, 0.f, 0.f, 0.f, 0.f, 0.f, 0.f, 0.f};
    int j = beg;
    for (; j + 7 < end; j += 8) {
        int s[8];
#pragma unroll
        for (int q = 0; q < 8; q++) s[q] = __ldg(&ep[j + q]);
        uint4 v[8];
#pragma unroll
        for (int q = 0; q < 8; q++) v[q] = __ldg(&fb[(size_t)s[q] * 8 + sl]);
#pragma unroll
        for (int q = 0; q < 8; q++) acc_h8(acc, v[q]);
    }
    for (; j + 3 < end; j += 4) {
        int s0 = __ldg(&ep[j]),     s1 = __ldg(&ep[j + 1]);
        int s2 = __ldg(&ep[j + 2]), s3 = __ldg(&ep[j + 3]);
        uint4 v0 = __ldg(&fb[(size_t)s0 * 8 + sl]);
        uint4 v1 = __ldg(&fb[(size_t)s1 * 8 + sl]);
        uint4 v2 = __ldg(&fb[(size_t)s2 * 8 + sl]);
        uint4 v3 = __ldg(&fb[(size_t)s3 * 8 + sl]);
        acc_h8(acc, v0); acc_h8(acc, v1); acc_h8(acc, v2); acc_h8(acc, v3);
    }
    for (; j < end; ++j) {
        int s0 = __ldg(&ep[j]);
        uint4 v0 = __ldg(&fb[(size_t)s0 * 8 + sl]);
        acc_h8(acc, v0);
    }
    float inv = 1.0f / fmaxf((float)deg, 1.0f);
    const float* yp = y2hi + (size_t)node * 64 + sl * 8;
    const float* bp = bl2 + sl * 8;
    float4 y0 = *(const float4*)yp, y1 = *(const float4*)(yp + 4);
    float4 b0 = *(const float4*)bp, b1 = *(const float4*)(bp + 4);
    float4 o0, o1;
    o0.x = 1.0f / (1.0f + __expf(-(acc[0] * inv + y0.x + b0.x)));
    o0.y = 1.0f / (1.0f + __expf(-(acc[1] * inv + y0.y + b0.y)));
    o0.z = 1.0f / (1.0f + __expf(-(acc[2] * inv + y0.z + b0.z)));
    o0.w = 1.0f / (1.0f + __expf(-(acc[3] * inv + y0.w + b0.w)));
    o1.x = 1.0f / (1.0f + __expf(-(acc[4] * inv + y1.x + b1.x)));
    o1.y = 1.0f / (1.0f + __expf(-(acc[5] * inv + y1.y + b1.y)));
    o1.z = 1.0f / (1.0f + __expf(-(acc[6] * inv + y1.z + b1.z)));
    o1.w = 1.0f / (1.0f + __expf(-(acc[7] * inv + y1.w + b1.w)));
    float* op = out + (size_t)node * 64 + sl * 8;
    *(float4*)op       = o0;
    *(float4*)(op + 4) = o1;
}

// ---------------------------------------------------------------------------
// FUSED GEMM over rows [base, nend):
//   phase 1: h = relu([mean|x] @ W1t + bl1)  -> SMEM (fp16 pairs, pad-68)
//   phase 2: y2 = h @ W2t                    -> y2bw (lo 64, fp16) / y2hi (f32)
// ---------------------------------------------------------------------------
#define P1_TILE 2560
#define W2S_OFF 10240
#define HS_OFF  18944
#define FUSED_SMEM_WORDS 27648

__global__ void __launch_bounds__(256, 2)
fused_gemm(const uint32_t* __restrict__ meanw, const uint32_t* __restrict__ xhw,
           const uint32_t* __restrict__ w1tw, const float* __restrict__ bl1,
           const uint32_t* __restrict__ w2tw,
           uint32_t* __restrict__ y2bw, float* __restrict__ y2hi,
           int base, int nend)
{
    extern __shared__ uint32_t smem[];
    const int tid  = threadIdx.x;
    const int wid  = tid >> 5;
    const int lane = tid & 31;
    const int wm   = wid & 1;
    const int wn   = wid >> 1;
    const int g    = lane >> 2;
    const int tg   = lane & 3;
    const int row0 = base + blockIdx.x * 128;

    const uint32_t sm_b = smem_u32(smem);

    float c[4][4][4];
#pragma unroll
    for (int mi = 0; mi < 4; mi++)
#pragma unroll
        for (int ni = 0; ni < 4; ni++)
#pragma unroll
            for (int j = 0; j < 4; j++) c[mi][ni][j] = 0.f;

    // -------- W2 tile load (own commit group, consumed in phase 2) --------
#pragma unroll
    for (int i = tid; i < 2048; i += 256) {            // 128 rows x 16 uint4
        int r = i >> 4, c4 = (i & 15) << 2;
        cp_async16(sm_b + (uint32_t)((W2S_OFF + r * 68 + c4) * 4),
                   w2tw + (size_t)r * 64 + c4, 16);
    }
    CP_COMMIT();

    // -------- phase 1: [mean|x] @ W1t, K=256 (8 chunks of 16 words) --------
    auto prefetch = [&](int ch, int stage) {
        const uint32_t* Aw = (ch < 4) ? meanw : xhw;
        int kkw = (ch & 3) * 16;
#pragma unroll
        for (int i = tid; i < 512; i += 256) {
            int r = i >> 2, g4 = (i & 3) << 2;
            int node = row0 + r;
            int ok = (node < nend);
            const uint32_t* gA = Aw + (size_t)(ok ? node : 0) * 64 + kkw + g4;
            cp_async16(sm_b + (uint32_t)((stage * P1_TILE + r * 20 + g4) * 4), gA, ok ? 16 : 0);
            const uint32_t* gW = w1tw + (size_t)r * 128 + ch * 16 + g4;
            cp_async16(sm_b + (uint32_t)(((2 + stage) * P1_TILE + r * 20 + g4) * 4), gW, 16);
        }
        CP_COMMIT();
    };

    prefetch(0, 0);

#pragma unroll 1
    for (int ch = 0; ch < 8; ++ch) {
        const int stage = ch & 1;
        if (ch + 1 < 8) {
            prefetch(ch + 1, stage ^ 1);
            CP_WAIT1();
        } else {
            CP_WAIT0();
        }
        __syncthreads();

        const uint32_t* Ab = smem + stage * P1_TILE;
        const uint32_t* Wb = smem + (2 + stage) * P1_TILE;

#pragma unroll
        for (int ks = 0; ks < 2; ++ks) {
            const int k0 = ks * 8;
            uint32_t a[4][4];
#pragma unroll
            for (int mi = 0; mi < 4; mi++) {
                int r0 = wm * 64 + mi * 16 + g;
                a[mi][0] = Ab[r0 * 20 + k0 + tg];
                a[mi][1] = Ab[(r0 + 8) * 20 + k0 + tg];
                a[mi][2] = Ab[r0 * 20 + k0 + tg + 4];
                a[mi][3] = Ab[(r0 + 8) * 20 + k0 + tg + 4];
            }
#pragma unroll
            for (int ni = 0; ni < 4; ni++) {
                int nb = wn * 32 + ni * 8 + g;
                uint32_t b[2];
                b[0] = Wb[nb * 20 + k0 + tg];
                b[1] = Wb[nb * 20 + k0 + tg + 4];
#pragma unroll
                for (int mi = 0; mi < 4; mi++)
                    mma_f16(c[mi][ni], a[mi], b);
            }
        }
        __syncthreads();
    }

    // -------- h = relu(c + bl1) -> SMEM (fp16 pairs) --------
#pragma unroll
    for (int mi = 0; mi < 4; mi++) {
#pragma unroll
        for (int half = 0; half < 2; half++) {
            int rl = wm * 64 + mi * 16 + g + half * 8;   // local row 0..127
#pragma unroll
            for (int ni = 0; ni < 4; ni++) {
                int col = wn * 32 + ni * 8 + tg * 2;
                float v0 = fmaxf(c[mi][ni][half * 2 + 0] + __ldg(&bl1[col]), 0.f);
                float v1 = fmaxf(c[mi][ni][half * 2 + 1] + __ldg(&bl1[col + 1]), 0.f);
                smem[HS_OFF + rl * 68 + (col >> 1)] = f2h2(v0, v1);
            }
        }
    }
    __syncthreads();

    // -------- phase 2: y2 = h @ W2t, K=128 --------
#pragma unroll
    for (int mi = 0; mi < 4; mi++)
#pragma unroll
        for (int ni = 0; ni < 4; ni++)
#pragma unroll
            for (int j = 0; j < 4; j++) c[mi][ni][j] = 0.f;

    const uint32_t* Hs  = smem + HS_OFF;
    const uint32_t* W2s = smem + W2S_OFF;
#pragma unroll
    for (int ks = 0; ks < 8; ++ks) {
        const int k0 = ks * 8;
        uint32_t a[4][4];
#pragma unroll
        for (int mi = 0; mi < 4; mi++) {
            int r0 = wm * 64 + mi * 16 + g;
            a[mi][0] = Hs[r0 * 68 + k0 + tg];
            a[mi][1] = Hs[(r0 + 8) * 68 + k0 + tg];
            a[mi][2] = Hs[r0 * 68 + k0 + tg + 4];
            a[mi][3] = Hs[(r0 + 8) * 68 + k0 + tg + 4];
        }
#pragma unroll
        for (int ni = 0; ni < 4; ni++) {
            int nb = wn * 32 + ni * 8 + g;
            uint32_t b[2];
            b[0] = W2s[nb * 68 + k0 + tg];
            b[1] = W2s[nb * 68 + k0 + tg + 4];
#pragma unroll
            for (int mi = 0; mi < 4; mi++)
                mma_f16(c[mi][ni], a[mi], b);
        }
    }

    // -------- epilogue --------
#pragma unroll
    for (int mi = 0; mi < 4; mi++) {
#pragma unroll
        for (int half = 0; half < 2; half++) {
            int row = row0 + wm * 64 + mi * 16 + g + half * 8;
            if (row < nend) {
#pragma unroll
                for (int ni = 0; ni < 4; ni++) {
                    int col = wn * 32 + ni * 8 + tg * 2;
                    float v0 = c[mi][ni][half * 2 + 0];
                    float v1 = c[mi][ni][half * 2 + 1];
                    if (col < 64) {
                        y2bw[(size_t)row * 32 + (col >> 1)] = f2h2(v0, v1);
                    } else {
                        *(float2*)(y2hi + (size_t)row * 64 + (col - 64)) =
                            make_float2(v0, v1);
                    }
                }
            }
        }
    }
}

// ---------------------------------------------------------------------------
extern "C" void kernel_launch(void* const* d_in, const int* in_sizes, int n_in,
                              void* d_out, int out_size) {
    const float* x   = (const float*)d_in[0];
    const void*  ei  = d_in[1];
    const float* Wl1 = (const float*)d_in[2];
    const float* bl1 = (const float*)d_in[3];
    const float* Wr1 = (const float*)d_in[4];
    const float* Wl2 = (const float*)d_in[5];
    const float* bl2 = (const float*)d_in[6];
    const float* Wr2 = (const float*)d_in[7];
    float* out = (float*)d_out;

    const int n  = in_sizes[0] / 128;   // 100000
    const int ne = in_sizes[1] / 2;     // 1600000

    uint32_t *meanw, *xhw, *y2bw, *w1tw, *w2tw;
    float *y2hi;
    int *cnt, *cur, *rowptr, *eidx, *total;
    cudaGetSymbolAddress((void**)&meanw,  g_meanw);
    cudaGetSymbolAddress((void**)&xhw,    g_xhw);
    cudaGetSymbolAddress((void**)&y2bw,   g_y2bw);
    cudaGetSymbolAddress((void**)&y2hi,   g_y2hi);
    cudaGetSymbolAddress((void**)&w1tw,   g_w1tw);
    cudaGetSymbolAddress((void**)&w2tw,   g_w2tw);
    cudaGetSymbolAddress((void**)&cnt,    g_cnt);
    cudaGetSymbolAddress((void**)&cur,    g_cur);
    cudaGetSymbolAddress((void**)&rowptr, g_rowptr);
    cudaGetSymbolAddress((void**)&eidx,   g_eidx);
    cudaGetSymbolAddress((void**)&total,  g_total);

    const int SMEM_BYTES = FUSED_SMEM_WORDS * 4;   // 108 KB
    cudaFuncSetAttribute(fused_gemm,
                         cudaFuncAttributeMaxDynamicSharedMemorySize, SMEM_BYTES);

    // asymmetric split: chunk A ~58% (keeps S1 busy until gather_B ends)
    const int n2    = ((int)(n * 0.58f + 127) / 128) * 128;
    const int nscan = (n + 511) / 512;
    const int eblk2 = (ne / 2 + 255) / 256 + 1;
    const int gblkA = (n2 + 15) / 16;
    const int gblkB = (n - n2 + 15) / 16;
    const int gblkF = (n + 31) / 32;
    const int mblkA = n2 / 128;
    const int mblkB = (n - n2 + 127) / 128;
    const int n32   = n * 32;
    const int pitems = n32 + 128 * 128 + 128 * 64;
    const int pblk  = (pitems + 255) / 256;

    // Fork resources (host-side only; intentionally not destroyed — capture-
    // referenced objects must outlive the graph).
    cudaStream_t sB;
    cudaStreamCreateWithFlags(&sB, cudaStreamNonBlocking);
    cudaEvent_t ev0, evP, evGA, ev2A;
    cudaEventCreateWithFlags(&ev0,  cudaEventDisableTiming);
    cudaEventCreateWithFlags(&evP,  cudaEventDisableTiming);
    cudaEventCreateWithFlags(&evGA, cudaEventDisableTiming);
    cudaEventCreateWithFlags(&ev2A, cudaEventDisableTiming);

    // ---- fork S1 at capture root: prep runs parallel with zero+CSR ----
    cudaEventRecord(ev0, 0);
    cudaStreamWaitEvent(sB, ev0, 0);
    prep_kernel<<<pblk, 256, 0, sB>>>(x, xhw, Wl1, Wr1, w1tw, Wl2, Wr2, w2tw, n32);
    cudaEventRecord(evP, sB);

    // ---- S0: zero cnt + detect, then CSR build ----
    zero_detect_kernel<<<(n + 255) / 256, 256>>>(cnt, (const int*)ei, n);
    hist_kernel<<<eblk2, 256>>>(ei, cnt, ne);
    scan_kernel<<<nscan, 512>>>(cnt, rowptr, cur, total, n);
    fill_kernel<<<eblk2, 256>>>(ei, cur, eidx, ne);

    // ---- S0: gather chunk A, then chunk B ----
    cudaStreamWaitEvent(0, evP, 0);
    gather_mean128_w<<<gblkA, 256>>>(xhw, rowptr, cnt, eidx, meanw, 0, n2);
    cudaEventRecord(evGA, 0);
    gather_mean128_w<<<gblkB, 256>>>(xhw, rowptr, cnt, eidx, meanw, n2, n);

    // ---- S1: fused GEMM for chunk A (overlaps gather_B) ----
    cudaStreamWaitEvent(sB, evGA, 0);
    fused_gemm<<<mblkA, 256, SMEM_BYTES, sB>>>(meanw, xhw, w1tw, bl1, w2tw,
                                               y2bw, y2hi, 0, n2);
    cudaEventRecord(ev2A, sB);

    // ---- S0: fused GEMM for chunk B ----
    fused_gemm<<<mblkB, 256, SMEM_BYTES>>>(meanw, xhw, w1tw, bl1, w2tw,
                                           y2bw, y2hi, n2, n);

    // ---- S0: join + final gather ----
    cudaStreamWaitEvent(0, ev2A, 0);
    gather_final64_w<<<gblkF, 256>>>(y2bw, y2hi, bl2, rowptr, cnt, eidx, out, n);
}

// round 15
// speedup vs baseline: 1.0740x; 1.0740x over previous
#include <cuda_runtime.h>
#include <cuda_fp16.h>
#include <cstdint>
#include <math.h>

// ---------------------------------------------------------------------------
// GraphSAGE 2-layer, all-fp16 intermediates, f32 accum.
// Direct-slot adjacency (no CSR scan): slot[d*128 + pos] = src, cnt[d] = deg.
// Gathers (fp16 payload, 16B-lane loads) + FUSED fp16 mma GEMMs (h in SMEM).
//   S0: zero+detect, fill_direct, g_A, g_B, fused_B, gather_final
//   S1: prep (from capture root), fused_A (overlaps g_B)
// ---------------------------------------------------------------------------

#define N_MAX 100000
#define E_MAX 1600000
#define MAXD  128

__device__ uint32_t g_meanw[(size_t)N_MAX * 64];   // mean1, fp16 pairs
__device__ uint32_t g_xhw  [(size_t)N_MAX * 64];   // fp16(x) pairs
__device__ uint32_t g_y2bw [(size_t)N_MAX * 32];   // y2 lo cols, fp16 pairs
__device__ float    g_y2hi [(size_t)N_MAX * 64];   // y2 hi cols, f32
__device__ uint32_t g_w1tw [128 * 128];            // [N=128][K=256] fp16 pairs
__device__ uint32_t g_w2tw [128 * 64];             // [N=128][K=128] fp16 pairs
__device__ int      g_cnt [N_MAX];
__device__ int      g_slot[(size_t)N_MAX * MAXD];  // direct adjacency slots
__device__ int      g_is64;

// ---------------- helpers ----------------
__device__ __forceinline__ float2 h2f2(uint32_t v) {
    __half2 h = *reinterpret_cast<__half2*>(&v);
    return __half22float2(h);
}
__device__ __forceinline__ uint32_t f2h2(float lo, float hi) {
    __half2 h = __floats2half2_rn(lo, hi);
    return *reinterpret_cast<uint32_t*>(&h);
}
__device__ __forceinline__ void mma_f16(float (&c)[4], const uint32_t (&a)[4],
                                        const uint32_t (&b)[2]) {
    asm volatile(
        "mma.sync.aligned.m16n8k16.row.col.f32.f16.f16.f32 "
        "{%0,%1,%2,%3}, {%4,%5,%6,%7}, {%8,%9}, {%0,%1,%2,%3};"
        : "+f"(c[0]), "+f"(c[1]), "+f"(c[2]), "+f"(c[3])
        : "r"(a[0]), "r"(a[1]), "r"(a[2]), "r"(a[3]), "r"(b[0]), "r"(b[1]));
}
__device__ __forceinline__ void acc_h8(float (&acc)[8], uint4 v) {
    float2 f0 = h2f2(v.x), f1 = h2f2(v.y);
    float2 f2 = h2f2(v.z), f3 = h2f2(v.w);
    acc[0] += f0.x; acc[1] += f0.y; acc[2] += f1.x; acc[3] += f1.y;
    acc[4] += f2.x; acc[5] += f2.y; acc[6] += f3.x; acc[7] += f3.y;
}
__device__ __forceinline__ uint32_t smem_u32(const void* p) {
    uint32_t a;
    asm("{ .reg .u64 t; cvta.to.shared.u64 t, %1; cvt.u32.u64 %0, t; }"
        : "=r"(a) : "l"(p));
    return a;
}
__device__ __forceinline__ void cp_async16(uint32_t smem, const void* g, int src_bytes) {
    asm volatile("cp.async.ca.shared.global [%0], [%1], 16, %2;"
                 :: "r"(smem), "l"(g), "r"(src_bytes) : "memory");
}
#define CP_COMMIT() asm volatile("cp.async.commit_group;" ::: "memory")
#define CP_WAIT0()  asm volatile("cp.async.wait_group 0;" ::: "memory")
#define CP_WAIT1()  asm volatile("cp.async.wait_group 1;" ::: "memory")

// ---------------- adjacency build ----------------
__device__ __forceinline__ int edge_at(const void* ei, long long idx, int is64) {
    if (is64) return (int)((const long long*)ei)[idx];
    return ((const int*)ei)[idx];
}
__global__ void zero_detect_kernel(int* __restrict__ cnt, const int* __restrict__ ei, int n) {
    int i = blockIdx.x * blockDim.x + threadIdx.x;
    if (i < n) cnt[i] = 0;
    if (i == 0) {
        int nz = 0;
        for (int q = 1; q < 256; q += 2) nz += (ei[q] != 0);
        g_is64 = (nz == 0) ? 1 : 0;
    }
}
// Direct slot fill: one pass, cnt doubles as cursor and final degree.
__global__ void fill_direct_kernel(const void* __restrict__ ei, int* __restrict__ cnt,
                                   int* __restrict__ slot, int ne) {
    int i = blockIdx.x * blockDim.x + threadIdx.x;
    int is64 = g_is64;
    int i2 = i * 2;
    if (((ne & 1) == 0) && i2 + 1 < ne) {
        int s0, s1, d0, d1;
        if (is64) {
            longlong2 sv = __ldg((const longlong2*)ei + i2 / 2);
            longlong2 dv = __ldg((const longlong2*)ei + (ne + i2) / 2);
            s0 = (int)sv.x; s1 = (int)sv.y;
            d0 = (int)dv.x; d1 = (int)dv.y;
        } else {
            int2 sv = __ldg((const int2*)ei + i2 / 2);
            int2 dv = __ldg((const int2*)ei + (ne + i2) / 2);
            s0 = sv.x; s1 = sv.y;
            d0 = dv.x; d1 = dv.y;
        }
        int p0 = atomicAdd(&cnt[d0], 1);
        if (p0 < MAXD) slot[(size_t)d0 * MAXD + p0] = s0;
        int p1 = atomicAdd(&cnt[d1], 1);
        if (p1 < MAXD) slot[(size_t)d1 * MAXD + p1] = s1;
    } else {
        for (int q = 0; q < 2; q++)
            if (i2 + q < ne) {
                int s = edge_at(ei, i2 + q, is64);
                int d = edge_at(ei, (long long)ne + i2 + q, is64);
                int p = atomicAdd(&cnt[d], 1);
                if (p < MAXD) slot[(size_t)d * MAXD + p] = s;
            }
    }
}

// ---------------- prep: x->fp16, W transposes (fp16 pairs) ----------------
__global__ void prep_kernel(const float* __restrict__ x, uint32_t* __restrict__ xhw,
                            const float* __restrict__ Wl1, const float* __restrict__ Wr1,
                            uint32_t* __restrict__ W1tw,
                            const float* __restrict__ Wl2, const float* __restrict__ Wr2,
                            uint32_t* __restrict__ W2tw, int n32) {
    int i = blockIdx.x * blockDim.x + threadIdx.x;
    if (i < n32) {
        float4 v = __ldg((const float4*)x + i);
        uint2 o;
        o.x = f2h2(v.x, v.y);
        o.y = f2h2(v.z, v.w);
        *((uint2*)xhw + i) = o;
        return;
    }
    int j = i - n32;
    if (j < 128 * 128) {                       // W1tw: [nn][w], k = 2w,2w+1 over 256
        int nn = j >> 7, w = j & 127;
        int k0 = 2 * w;
        float v0, v1;
        if (k0 < 128) { v0 = Wl1[k0 * 128 + nn]; v1 = Wl1[(k0 + 1) * 128 + nn]; }
        else          { v0 = Wr1[(k0 - 128) * 128 + nn]; v1 = Wr1[(k0 - 127) * 128 + nn]; }
        W1tw[j] = f2h2(v0, v1);
    } else if (j < 128 * 128 + 128 * 64) {     // W2tw: [nn][w], k = 2w,2w+1 over 128
        int jj = j - 128 * 128;
        int nn = jj >> 6, w = jj & 63;
        int k0 = 2 * w;
        float v0, v1;
        if (nn < 64) { v0 = Wl2[k0 * 64 + nn];        v1 = Wl2[(k0 + 1) * 64 + nn]; }
        else         { v0 = Wr2[k0 * 64 + (nn - 64)]; v1 = Wr2[(k0 + 1) * 64 + (nn - 64)]; }
        W2tw[jj] = f2h2(v0, v1);
    }
}

// ---------------- wide gathers (direct slots, range [base, nend)) ----------
__global__ void gather_mean128_w(const uint32_t* __restrict__ featw,
                                 const int* __restrict__ cnt,
                                 const int* __restrict__ slot,
                                 uint32_t* __restrict__ meanw, int base, int nend) {
    int gw   = (blockIdx.x * blockDim.x + threadIdx.x) >> 5;
    int lane = threadIdx.x & 31;
    int node = base + gw * 2 + (lane >> 4);
    int sl   = lane & 15;
    if (node >= nend) return;
    int deg = __ldg(&cnt[node]);
    int end = (deg < MAXD) ? deg : MAXD;
    const int* ep = slot + (size_t)node * MAXD;
    const uint4* fb = (const uint4*)featw;   // 16 uint4 per row
    float acc[8] = {0.f, 0.f, 0.f, 0.f, 0.f, 0.f, 0.f, 0.f};
    int j = 0;
    for (; j + 3 < end; j += 4) {
        int s0 = __ldg(&ep[j]),     s1 = __ldg(&ep[j + 1]);
        int s2 = __ldg(&ep[j + 2]), s3 = __ldg(&ep[j + 3]);
        uint4 v0 = __ldg(&fb[(size_t)s0 * 16 + sl]);
        uint4 v1 = __ldg(&fb[(size_t)s1 * 16 + sl]);
        uint4 v2 = __ldg(&fb[(size_t)s2 * 16 + sl]);
        uint4 v3 = __ldg(&fb[(size_t)s3 * 16 + sl]);
        acc_h8(acc, v0); acc_h8(acc, v1); acc_h8(acc, v2); acc_h8(acc, v3);
    }
    for (; j < end; ++j) {
        int s0 = __ldg(&ep[j]);
        uint4 v0 = __ldg(&fb[(size_t)s0 * 16 + sl]);
        acc_h8(acc, v0);
    }
    float inv = 1.0f / fmaxf((float)deg, 1.0f);
    uint4 o;
    o.x = f2h2(acc[0] * inv, acc[1] * inv);
    o.y = f2h2(acc[2] * inv, acc[3] * inv);
    o.z = f2h2(acc[4] * inv, acc[5] * inv);
    o.w = f2h2(acc[6] * inv, acc[7] * inv);
    *(uint4*)(meanw + (size_t)node * 64 + sl * 4) = o;
}

// gather_final: quarter-warp per node, unroll-8.
__global__ void gather_final64_w(const uint32_t* __restrict__ y2bw,
                                 const float* __restrict__ y2hi,
                                 const float* __restrict__ bl2,
                                 const int* __restrict__ cnt,
                                 const int* __restrict__ slot,
                                 float* __restrict__ out, int n) {
    int gw   = (blockIdx.x * blockDim.x + threadIdx.x) >> 5;
    int lane = threadIdx.x & 31;
    int node = gw * 4 + (lane >> 3);
    int sl   = lane & 7;
    if (node >= n) return;
    int deg = __ldg(&cnt[node]);
    int end = (deg < MAXD) ? deg : MAXD;
    const int* ep = slot + (size_t)node * MAXD;
    const uint4* fb = (const uint4*)y2bw;    // 8 uint4 per row
    float acc[8] = {0.f, 0.f, 0.f, 0.f, 0.f, 0.f, 0.f, 0.f};
    int j = 0;
    for (; j + 7 < end; j += 8) {
        int s[8];
#pragma unroll
        for (int q = 0; q < 8; q++) s[q] = __ldg(&ep[j + q]);
        uint4 v[8];
#pragma unroll
        for (int q = 0; q < 8; q++) v[q] = __ldg(&fb[(size_t)s[q] * 8 + sl]);
#pragma unroll
        for (int q = 0; q < 8; q++) acc_h8(acc, v[q]);
    }
    for (; j + 3 < end; j += 4) {
        int s0 = __ldg(&ep[j]),     s1 = __ldg(&ep[j + 1]);
        int s2 = __ldg(&ep[j + 2]), s3 = __ldg(&ep[j + 3]);
        uint4 v0 = __ldg(&fb[(size_t)s0 * 8 + sl]);
        uint4 v1 = __ldg(&fb[(size_t)s1 * 8 + sl]);
        uint4 v2 = __ldg(&fb[(size_t)s2 * 8 + sl]);
        uint4 v3 = __ldg(&fb[(size_t)s3 * 8 + sl]);
        acc_h8(acc, v0); acc_h8(acc, v1); acc_h8(acc, v2); acc_h8(acc, v3);
    }
    for (; j < end; ++j) {
        int s0 = __ldg(&ep[j]);
        uint4 v0 = __ldg(&fb[(size_t)s0 * 8 + sl]);
        acc_h8(acc, v0);
    }
    float inv = 1.0f / fmaxf((float)deg, 1.0f);
    const float* yp = y2hi + (size_t)node * 64 + sl * 8;
    const float* bp = bl2 + sl * 8;
    float4 y0 = *(const float4*)yp, y1 = *(const float4*)(yp + 4);
    float4 b0 = *(const float4*)bp, b1 = *(const float4*)(bp + 4);
    float4 o0, o1;
    o0.x = 1.0f / (1.0f + __expf(-(acc[0] * inv + y0.x + b0.x)));
    o0.y = 1.0f / (1.0f + __expf(-(acc[1] * inv + y0.y + b0.y)));
    o0.z = 1.0f / (1.0f + __expf(-(acc[2] * inv + y0.z + b0.z)));
    o0.w = 1.0f / (1.0f + __expf(-(acc[3] * inv + y0.w + b0.w)));
    o1.x = 1.0f / (1.0f + __expf(-(acc[4] * inv + y1.x + b1.x)));
    o1.y = 1.0f / (1.0f + __expf(-(acc[5] * inv + y1.y + b1.y)));
    o1.z = 1.0f / (1.0f + __expf(-(acc[6] * inv + y1.z + b1.z)));
    o1.w = 1.0f / (1.0f + __expf(-(acc[7] * inv + y1.w + b1.w)));
    float* op = out + (size_t)node * 64 + sl * 8;
    *(float4*)op       = o0;
    *(float4*)(op + 4) = o1;
}

// ---------------------------------------------------------------------------
// FUSED GEMM over rows [base, nend):
//   phase 1: h = relu([mean|x] @ W1t + bl1)  -> SMEM (fp16 pairs, pad-68)
//   phase 2: y2 = h @ W2t                    -> y2bw (lo 64, fp16) / y2hi (f32)
// ---------------------------------------------------------------------------
#define P1_TILE 2560
#define W2S_OFF 10240
#define HS_OFF  18944
#define FUSED_SMEM_WORDS 27648

__global__ void __launch_bounds__(256, 2)
fused_gemm(const uint32_t* __restrict__ meanw, const uint32_t* __restrict__ xhw,
           const uint32_t* __restrict__ w1tw, const float* __restrict__ bl1,
           const uint32_t* __restrict__ w2tw,
           uint32_t* __restrict__ y2bw, float* __restrict__ y2hi,
           int base, int nend)
{
    extern __shared__ uint32_t smem[];
    const int tid  = threadIdx.x;
    const int wid  = tid >> 5;
    const int lane = tid & 31;
    const int wm   = wid & 1;
    const int wn   = wid >> 1;
    const int g    = lane >> 2;
    const int tg   = lane & 3;
    const int row0 = base + blockIdx.x * 128;

    const uint32_t sm_b = smem_u32(smem);

    float c[4][4][4];
#pragma unroll
    for (int mi = 0; mi < 4; mi++)
#pragma unroll
        for (int ni = 0; ni < 4; ni++)
#pragma unroll
            for (int j = 0; j < 4; j++) c[mi][ni][j] = 0.f;

    // -------- W2 tile load (own commit group, consumed in phase 2) --------
#pragma unroll
    for (int i = tid; i < 2048; i += 256) {            // 128 rows x 16 uint4
        int r = i >> 4, c4 = (i & 15) << 2;
        cp_async16(sm_b + (uint32_t)((W2S_OFF + r * 68 + c4) * 4),
                   w2tw + (size_t)r * 64 + c4, 16);
    }
    CP_COMMIT();

    // -------- phase 1: [mean|x] @ W1t, K=256 (8 chunks of 16 words) --------
    auto prefetch = [&](int ch, int stage) {
        const uint32_t* Aw = (ch < 4) ? meanw : xhw;
        int kkw = (ch & 3) * 16;
#pragma unroll
        for (int i = tid; i < 512; i += 256) {
            int r = i >> 2, g4 = (i & 3) << 2;
            int node = row0 + r;
            int ok = (node < nend);
            const uint32_t* gA = Aw + (size_t)(ok ? node : 0) * 64 + kkw + g4;
            cp_async16(sm_b + (uint32_t)((stage * P1_TILE + r * 20 + g4) * 4), gA, ok ? 16 : 0);
            const uint32_t* gW = w1tw + (size_t)r * 128 + ch * 16 + g4;
            cp_async16(sm_b + (uint32_t)(((2 + stage) * P1_TILE + r * 20 + g4) * 4), gW, 16);
        }
        CP_COMMIT();
    };

    prefetch(0, 0);

#pragma unroll 1
    for (int ch = 0; ch < 8; ++ch) {
        const int stage = ch & 1;
        if (ch + 1 < 8) {
            prefetch(ch + 1, stage ^ 1);
            CP_WAIT1();
        } else {
            CP_WAIT0();
        }
        __syncthreads();

        const uint32_t* Ab = smem + stage * P1_TILE;
        const uint32_t* Wb = smem + (2 + stage) * P1_TILE;

#pragma unroll
        for (int ks = 0; ks < 2; ++ks) {
            const int k0 = ks * 8;
            uint32_t a[4][4];
#pragma unroll
            for (int mi = 0; mi < 4; mi++) {
                int r0 = wm * 64 + mi * 16 + g;
                a[mi][0] = Ab[r0 * 20 + k0 + tg];
                a[mi][1] = Ab[(r0 + 8) * 20 + k0 + tg];
                a[mi][2] = Ab[r0 * 20 + k0 + tg + 4];
                a[mi][3] = Ab[(r0 + 8) * 20 + k0 + tg + 4];
            }
#pragma unroll
            for (int ni = 0; ni < 4; ni++) {
                int nb = wn * 32 + ni * 8 + g;
                uint32_t b[2];
                b[0] = Wb[nb * 20 + k0 + tg];
                b[1] = Wb[nb * 20 + k0 + tg + 4];
#pragma unroll
                for (int mi = 0; mi < 4; mi++)
                    mma_f16(c[mi][ni], a[mi], b);
            }
        }
        __syncthreads();
    }

    // -------- h = relu(c + bl1) -> SMEM (fp16 pairs) --------
#pragma unroll
    for (int mi = 0; mi < 4; mi++) {
#pragma unroll
        for (int half = 0; half < 2; half++) {
            int rl = wm * 64 + mi * 16 + g + half * 8;   // local row 0..127
#pragma unroll
            for (int ni = 0; ni < 4; ni++) {
                int col = wn * 32 + ni * 8 + tg * 2;
                float v0 = fmaxf(c[mi][ni][half * 2 + 0] + __ldg(&bl1[col]), 0.f);
                float v1 = fmaxf(c[mi][ni][half * 2 + 1] + __ldg(&bl1[col + 1]), 0.f);
                smem[HS_OFF + rl * 68 + (col >> 1)] = f2h2(v0, v1);
            }
        }
    }
    __syncthreads();

    // -------- phase 2: y2 = h @ W2t, K=128 --------
#pragma unroll
    for (int mi = 0; mi < 4; mi++)
#pragma unroll
        for (int ni = 0; ni < 4; ni++)
#pragma unroll
            for (int j = 0; j < 4; j++) c[mi][ni][j] = 0.f;

    const uint32_t* Hs  = smem + HS_OFF;
    const uint32_t* W2s = smem + W2S_OFF;
#pragma unroll
    for (int ks = 0; ks < 8; ++ks) {
        const int k0 = ks * 8;
        uint32_t a[4][4];
#pragma unroll
        for (int mi = 0; mi < 4; mi++) {
            int r0 = wm * 64 + mi * 16 + g;
            a[mi][0] = Hs[r0 * 68 + k0 + tg];
            a[mi][1] = Hs[(r0 + 8) * 68 + k0 + tg];
            a[mi][2] = Hs[r0 * 68 + k0 + tg + 4];
            a[mi][3] = Hs[(r0 + 8) * 68 + k0 + tg + 4];
        }
#pragma unroll
        for (int ni = 0; ni < 4; ni++) {
            int nb = wn * 32 + ni * 8 + g;
            uint32_t b[2];
            b[0] = W2s[nb * 68 + k0 + tg];
            b[1] = W2s[nb * 68 + k0 + tg + 4];
#pragma unroll
            for (int mi = 0; mi < 4; mi++)
                mma_f16(c[mi][ni], a[mi], b);
        }
    }

    // -------- epilogue --------
#pragma unroll
    for (int mi = 0; mi < 4; mi++) {
#pragma unroll
        for (int half = 0; half < 2; half++) {
            int row = row0 + wm * 64 + mi * 16 + g + half * 8;
            if (row < nend) {
#pragma unroll
                for (int ni = 0; ni < 4; ni++) {
                    int col = wn * 32 + ni * 8 + tg * 2;
                    float v0 = c[mi][ni][half * 2 + 0];
                    float v1 = c[mi][ni][half * 2 + 1];
                    if (col < 64) {
                        y2bw[(size_t)row * 32 + (col >> 1)] = f2h2(v0, v1);
                    } else {
                        *(float2*)(y2hi + (size_t)row * 64 + (col - 64)) =
                            make_float2(v0, v1);
                    }
                }
            }
        }
    }
}

// ---------------------------------------------------------------------------
extern "C" void kernel_launch(void* const* d_in, const int* in_sizes, int n_in,
                              void* d_out, int out_size) {
    const float* x   = (const float*)d_in[0];
    const void*  ei  = d_in[1];
    const float* Wl1 = (const float*)d_in[2];
    const float* bl1 = (const float*)d_in[3];
    const float* Wr1 = (const float*)d_in[4];
    const float* Wl2 = (const float*)d_in[5];
    const float* bl2 = (const float*)d_in[6];
    const float* Wr2 = (const float*)d_in[7];
    float* out = (float*)d_out;

    const int n  = in_sizes[0] / 128;   // 100000
    const int ne = in_sizes[1] / 2;     // 1600000

    uint32_t *meanw, *xhw, *y2bw, *w1tw, *w2tw;
    float *y2hi;
    int *cnt, *slot;
    cudaGetSymbolAddress((void**)&meanw,  g_meanw);
    cudaGetSymbolAddress((void**)&xhw,    g_xhw);
    cudaGetSymbolAddress((void**)&y2bw,   g_y2bw);
    cudaGetSymbolAddress((void**)&y2hi,   g_y2hi);
    cudaGetSymbolAddress((void**)&w1tw,   g_w1tw);
    cudaGetSymbolAddress((void**)&w2tw,   g_w2tw);
    cudaGetSymbolAddress((void**)&cnt,    g_cnt);
    cudaGetSymbolAddress((void**)&slot,   g_slot);

    const int SMEM_BYTES = FUSED_SMEM_WORDS * 4;   // 108 KB
    cudaFuncSetAttribute(fused_gemm,
                         cudaFuncAttributeMaxDynamicSharedMemorySize, SMEM_BYTES);

    const int n2    = ((n / 2 + 127) / 128) * 128;   // 0.5 split (R13-proven)
    const int eblk2 = (ne / 2 + 255) / 256 + 1;
    const int gblkA = (n2 + 15) / 16;
    const int gblkB = (n - n2 + 15) / 16;
    const int gblkF = (n + 31) / 32;
    const int mblkA = n2 / 128;
    const int mblkB = (n - n2 + 127) / 128;
    const int n32   = n * 32;
    const int pitems = n32 + 128 * 128 + 128 * 64;
    const int pblk  = (pitems + 255) / 256;

    // Fork resources (host-side only; intentionally not destroyed — capture-
    // referenced objects must outlive the graph).
    cudaStream_t sB;
    cudaStreamCreateWithFlags(&sB, cudaStreamNonBlocking);
    cudaEvent_t ev0, evP, evGA, ev2A;
    cudaEventCreateWithFlags(&ev0,  cudaEventDisableTiming);
    cudaEventCreateWithFlags(&evP,  cudaEventDisableTiming);
    cudaEventCreateWithFlags(&evGA, cudaEventDisableTiming);
    cudaEventCreateWithFlags(&ev2A, cudaEventDisableTiming);

    // ---- fork S1 at capture root: prep runs parallel with adjacency build ----
    cudaEventRecord(ev0, 0);
    cudaStreamWaitEvent(sB, ev0, 0);
    prep_kernel<<<pblk, 256, 0, sB>>>(x, xhw, Wl1, Wr1, w1tw, Wl2, Wr2, w2tw, n32);
    cudaEventRecord(evP, sB);

    // ---- S0: zero cnt + detect, then single-pass slot fill ----
    zero_detect_kernel<<<(n + 255) / 256, 256>>>(cnt, (const int*)ei, n);
    fill_direct_kernel<<<eblk2, 256>>>(ei, cnt, slot, ne);

    // ---- S0: gather half A, then half B ----
    cudaStreamWaitEvent(0, evP, 0);
    gather_mean128_w<<<gblkA, 256>>>(xhw, cnt, slot, meanw, 0, n2);
    cudaEventRecord(evGA, 0);
    gather_mean128_w<<<gblkB, 256>>>(xhw, cnt, slot, meanw, n2, n);

    // ---- S1: fused GEMM for half A (overlaps gather_B) ----
    cudaStreamWaitEvent(sB, evGA, 0);
    fused_gemm<<<mblkA, 256, SMEM_BYTES, sB>>>(meanw, xhw, w1tw, bl1, w2tw,
                                               y2bw, y2hi, 0, n2);
    cudaEventRecord(ev2A, sB);

    // ---- S0: fused GEMM for half B ----
    fused_gemm<<<mblkB, 256, SMEM_BYTES>>>(meanw, xhw, w1tw, bl1, w2tw,
                                           y2bw, y2hi, n2, n);

    // ---- S0: join + final gather ----
    cudaStreamWaitEvent(0, ev2A, 0);
    gather_final64_w<<<gblkF, 256>>>(y2bw, y2hi, bl2, cnt, slot, out, n);
}

// round 16
// speedup vs baseline: 1.1155x; 1.0386x over previous
#include <cuda_runtime.h>
#include <cuda_fp16.h>
#include <cstdint>
#include <math.h>

// ---------------------------------------------------------------------------
// GraphSAGE 2-layer, all-fp16 intermediates, f32 accum (fp16 group-8 partial
// sums in gathers). Direct-slot adjacency. FUSED fp16 mma GEMMs (h in SMEM).
//   S0: zero+detect, fill_direct, g_A, g_B, fused_B, gather_final
//   S1: prep (from capture root), fused_A (overlaps g_B)
// ---------------------------------------------------------------------------

#define N_MAX 100000
#define E_MAX 1600000
#define MAXD  128

__device__ uint32_t g_meanw[(size_t)N_MAX * 64];   // mean1, fp16 pairs
__device__ uint32_t g_xhw  [(size_t)N_MAX * 64];   // fp16(x) pairs
__device__ uint32_t g_y2bw [(size_t)N_MAX * 32];   // y2 lo cols, fp16 pairs
__device__ float    g_y2hi [(size_t)N_MAX * 64];   // y2 hi cols, f32
__device__ uint32_t g_w1tw [128 * 128];            // [N=128][K=256] fp16 pairs
__device__ uint32_t g_w2tw [128 * 64];             // [N=128][K=128] fp16 pairs
__device__ int      g_cnt [N_MAX];
__device__ int      g_slot[(size_t)N_MAX * MAXD];  // direct adjacency slots
__device__ int      g_is64;

// ---------------- helpers ----------------
__device__ __forceinline__ __half2 u2h2(uint32_t v) {
    return *reinterpret_cast<__half2*>(&v);
}
__device__ __forceinline__ float2 h2f2(uint32_t v) {
    __half2 h = *reinterpret_cast<__half2*>(&v);
    return __half22float2(h);
}
__device__ __forceinline__ uint32_t f2h2(float lo, float hi) {
    __half2 h = __floats2half2_rn(lo, hi);
    return *reinterpret_cast<uint32_t*>(&h);
}
__device__ __forceinline__ void mma_f16(float (&c)[4], const uint32_t (&a)[4],
                                        const uint32_t (&b)[2]) {
    asm volatile(
        "mma.sync.aligned.m16n8k16.row.col.f32.f16.f16.f32 "
        "{%0,%1,%2,%3}, {%4,%5,%6,%7}, {%8,%9}, {%0,%1,%2,%3};"
        : "+f"(c[0]), "+f"(c[1]), "+f"(c[2]), "+f"(c[3])
        : "r"(a[0]), "r"(a[1]), "r"(a[2]), "r"(a[3]), "r"(b[0]), "r"(b[1]));
}
__device__ __forceinline__ void acc_h8(float (&acc)[8], uint4 v) {
    float2 f0 = h2f2(v.x), f1 = h2f2(v.y);
    float2 f2 = h2f2(v.z), f3 = h2f2(v.w);
    acc[0] += f0.x; acc[1] += f0.y; acc[2] += f1.x; acc[3] += f1.y;
    acc[4] += f2.x; acc[5] += f2.y; acc[6] += f3.x; acc[7] += f3.y;
}
// fp16 group-8 accumulation: 4 HADD2 per neighbor, one f32 flush per group.
__device__ __forceinline__ void acc_group8(float (&acc)[8], const uint4 (&v)[8]) {
    __half2 h0 = u2h2(v[0].x), h1 = u2h2(v[0].y);
    __half2 h2 = u2h2(v[0].z), h3 = u2h2(v[0].w);
#pragma unroll
    for (int q = 1; q < 8; q++) {
        h0 = __hadd2(h0, u2h2(v[q].x));
        h1 = __hadd2(h1, u2h2(v[q].y));
        h2 = __hadd2(h2, u2h2(v[q].z));
        h3 = __hadd2(h3, u2h2(v[q].w));
    }
    float2 f0 = __half22float2(h0), f1 = __half22float2(h1);
    float2 f2 = __half22float2(h2), f3 = __half22float2(h3);
    acc[0] += f0.x; acc[1] += f0.y; acc[2] += f1.x; acc[3] += f1.y;
    acc[4] += f2.x; acc[5] += f2.y; acc[6] += f3.x; acc[7] += f3.y;
}
__device__ __forceinline__ uint32_t smem_u32(const void* p) {
    uint32_t a;
    asm("{ .reg .u64 t; cvta.to.shared.u64 t, %1; cvt.u32.u64 %0, t; }"
        : "=r"(a) : "l"(p));
    return a;
}
__device__ __forceinline__ void cp_async16(uint32_t smem, const void* g, int src_bytes) {
    asm volatile("cp.async.ca.shared.global [%0], [%1], 16, %2;"
                 :: "r"(smem), "l"(g), "r"(src_bytes) : "memory");
}
#define CP_COMMIT() asm volatile("cp.async.commit_group;" ::: "memory")
#define CP_WAIT0()  asm volatile("cp.async.wait_group 0;" ::: "memory")
#define CP_WAIT1()  asm volatile("cp.async.wait_group 1;" ::: "memory")

// ---------------- adjacency build ----------------
__device__ __forceinline__ int edge_at(const void* ei, long long idx, int is64) {
    if (is64) return (int)((const long long*)ei)[idx];
    return ((const int*)ei)[idx];
}
__global__ void zero_detect_kernel(int* __restrict__ cnt, const int* __restrict__ ei, int n) {
    int i = blockIdx.x * blockDim.x + threadIdx.x;
    if (i < n) cnt[i] = 0;
    if (i == 0) {
        int nz = 0;
        for (int q = 1; q < 256; q += 2) nz += (ei[q] != 0);
        g_is64 = (nz == 0) ? 1 : 0;
    }
}
__global__ void fill_direct_kernel(const void* __restrict__ ei, int* __restrict__ cnt,
                                   int* __restrict__ slot, int ne) {
    int i = blockIdx.x * blockDim.x + threadIdx.x;
    int is64 = g_is64;
    int i2 = i * 2;
    if (((ne & 1) == 0) && i2 + 1 < ne) {
        int s0, s1, d0, d1;
        if (is64) {
            longlong2 sv = __ldg((const longlong2*)ei + i2 / 2);
            longlong2 dv = __ldg((const longlong2*)ei + (ne + i2) / 2);
            s0 = (int)sv.x; s1 = (int)sv.y;
            d0 = (int)dv.x; d1 = (int)dv.y;
        } else {
            int2 sv = __ldg((const int2*)ei + i2 / 2);
            int2 dv = __ldg((const int2*)ei + (ne + i2) / 2);
            s0 = sv.x; s1 = sv.y;
            d0 = dv.x; d1 = dv.y;
        }
        int p0 = atomicAdd(&cnt[d0], 1);
        if (p0 < MAXD) slot[(size_t)d0 * MAXD + p0] = s0;
        int p1 = atomicAdd(&cnt[d1], 1);
        if (p1 < MAXD) slot[(size_t)d1 * MAXD + p1] = s1;
    } else {
        for (int q = 0; q < 2; q++)
            if (i2 + q < ne) {
                int s = edge_at(ei, i2 + q, is64);
                int d = edge_at(ei, (long long)ne + i2 + q, is64);
                int p = atomicAdd(&cnt[d], 1);
                if (p < MAXD) slot[(size_t)d * MAXD + p] = s;
            }
    }
}

// ---------------- prep: x->fp16, W transposes (fp16 pairs) ----------------
__global__ void prep_kernel(const float* __restrict__ x, uint32_t* __restrict__ xhw,
                            const float* __restrict__ Wl1, const float* __restrict__ Wr1,
                            uint32_t* __restrict__ W1tw,
                            const float* __restrict__ Wl2, const float* __restrict__ Wr2,
                            uint32_t* __restrict__ W2tw, int n32) {
    int i = blockIdx.x * blockDim.x + threadIdx.x;
    if (i < n32) {
        float4 v = __ldg((const float4*)x + i);
        uint2 o;
        o.x = f2h2(v.x, v.y);
        o.y = f2h2(v.z, v.w);
        *((uint2*)xhw + i) = o;
        return;
    }
    int j = i - n32;
    if (j < 128 * 128) {                       // W1tw: [nn][w], k = 2w,2w+1 over 256
        int nn = j >> 7, w = j & 127;
        int k0 = 2 * w;
        float v0, v1;
        if (k0 < 128) { v0 = Wl1[k0 * 128 + nn]; v1 = Wl1[(k0 + 1) * 128 + nn]; }
        else          { v0 = Wr1[(k0 - 128) * 128 + nn]; v1 = Wr1[(k0 - 127) * 128 + nn]; }
        W1tw[j] = f2h2(v0, v1);
    } else if (j < 128 * 128 + 128 * 64) {     // W2tw: [nn][w], k = 2w,2w+1 over 128
        int jj = j - 128 * 128;
        int nn = jj >> 6, w = jj & 63;
        int k0 = 2 * w;
        float v0, v1;
        if (nn < 64) { v0 = Wl2[k0 * 64 + nn];        v1 = Wl2[(k0 + 1) * 64 + nn]; }
        else         { v0 = Wr2[k0 * 64 + (nn - 64)]; v1 = Wr2[(k0 + 1) * 64 + (nn - 64)]; }
        W2tw[jj] = f2h2(v0, v1);
    }
}

// ---------------- wide gathers (direct slots, range [base, nend)) ----------
__global__ void gather_mean128_w(const uint32_t* __restrict__ featw,
                                 const int* __restrict__ cnt,
                                 const int* __restrict__ slot,
                                 uint32_t* __restrict__ meanw, int base, int nend) {
    int gw   = (blockIdx.x * blockDim.x + threadIdx.x) >> 5;
    int lane = threadIdx.x & 31;
    int node = base + gw * 2 + (lane >> 4);
    int sl   = lane & 15;
    if (node >= nend) return;
    int deg = __ldg(&cnt[node]);
    int end = (deg < MAXD) ? deg : MAXD;
    const int* ep = slot + (size_t)node * MAXD;
    const uint4* fb = (const uint4*)featw;   // 16 uint4 per row
    float acc[8] = {0.f, 0.f, 0.f, 0.f, 0.f, 0.f, 0.f, 0.f};
    int j = 0;
    for (; j + 7 < end; j += 8) {
        int s[8];
#pragma unroll
        for (int q = 0; q < 8; q++) s[q] = __ldg(&ep[j + q]);
        uint4 v[8];
#pragma unroll
        for (int q = 0; q < 8; q++) v[q] = __ldg(&fb[(size_t)s[q] * 16 + sl]);
        acc_group8(acc, v);
    }
    for (; j < end; ++j) {
        int s0 = __ldg(&ep[j]);
        uint4 v0 = __ldg(&fb[(size_t)s0 * 16 + sl]);
        acc_h8(acc, v0);
    }
    float inv = 1.0f / fmaxf((float)deg, 1.0f);
    uint4 o;
    o.x = f2h2(acc[0] * inv, acc[1] * inv);
    o.y = f2h2(acc[2] * inv, acc[3] * inv);
    o.z = f2h2(acc[4] * inv, acc[5] * inv);
    o.w = f2h2(acc[6] * inv, acc[7] * inv);
    *(uint4*)(meanw + (size_t)node * 64 + sl * 4) = o;
}

// gather_final: quarter-warp per node, fp16 group-8 accumulation.
__global__ void gather_final64_w(const uint32_t* __restrict__ y2bw,
                                 const float* __restrict__ y2hi,
                                 const float* __restrict__ bl2,
                                 const int* __restrict__ cnt,
                                 const int* __restrict__ slot,
                                 float* __restrict__ out, int n) {
    int gw   = (blockIdx.x * blockDim.x + threadIdx.x) >> 5;
    int lane = threadIdx.x & 31;
    int node = gw * 4 + (lane >> 3);
    int sl   = lane & 7;
    if (node >= n) return;
    int deg = __ldg(&cnt[node]);
    int end = (deg < MAXD) ? deg : MAXD;
    const int* ep = slot + (size_t)node * MAXD;
    const uint4* fb = (const uint4*)y2bw;    // 8 uint4 per row
    float acc[8] = {0.f, 0.f, 0.f, 0.f, 0.f, 0.f, 0.f, 0.f};
    int j = 0;
    for (; j + 7 < end; j += 8) {
        int s[8];
#pragma unroll
        for (int q = 0; q < 8; q++) s[q] = __ldg(&ep[j + q]);
        uint4 v[8];
#pragma unroll
        for (int q = 0; q < 8; q++) v[q] = __ldg(&fb[(size_t)s[q] * 8 + sl]);
        acc_group8(acc, v);
    }
    for (; j < end; ++j) {
        int s0 = __ldg(&ep[j]);
        uint4 v0 = __ldg(&fb[(size_t)s0 * 8 + sl]);
        acc_h8(acc, v0);
    }
    float inv = 1.0f / fmaxf((float)deg, 1.0f);
    const float* yp = y2hi + (size_t)node * 64 + sl * 8;
    const float* bp = bl2 + sl * 8;
    float4 y0 = *(const float4*)yp, y1 = *(const float4*)(yp + 4);
    float4 b0 = *(const float4*)bp, b1 = *(const float4*)(bp + 4);
    float4 o0, o1;
    o0.x = 1.0f / (1.0f + __expf(-(acc[0] * inv + y0.x + b0.x)));
    o0.y = 1.0f / (1.0f + __expf(-(acc[1] * inv + y0.y + b0.y)));
    o0.z = 1.0f / (1.0f + __expf(-(acc[2] * inv + y0.z + b0.z)));
    o0.w = 1.0f / (1.0f + __expf(-(acc[3] * inv + y0.w + b0.w)));
    o1.x = 1.0f / (1.0f + __expf(-(acc[4] * inv + y1.x + b1.x)));
    o1.y = 1.0f / (1.0f + __expf(-(acc[5] * inv + y1.y + b1.y)));
    o1.z = 1.0f / (1.0f + __expf(-(acc[6] * inv + y1.z + b1.z)));
    o1.w = 1.0f / (1.0f + __expf(-(acc[7] * inv + y1.w + b1.w)));
    float* op = out + (size_t)node * 64 + sl * 8;
    *(float4*)op       = o0;
    *(float4*)(op + 4) = o1;
}

// ---------------------------------------------------------------------------
// FUSED GEMM over rows [base, nend):
//   phase 1: h = relu([mean|x] @ W1t + bl1)  -> SMEM (fp16 pairs, pad-68)
//   phase 2: y2 = h @ W2t                    -> y2bw (lo 64, fp16) / y2hi (f32)
// ---------------------------------------------------------------------------
#define P1_TILE 2560
#define W2S_OFF 10240
#define HS_OFF  18944
#define FUSED_SMEM_WORDS 27648

__global__ void __launch_bounds__(256, 2)
fused_gemm(const uint32_t* __restrict__ meanw, const uint32_t* __restrict__ xhw,
           const uint32_t* __restrict__ w1tw, const float* __restrict__ bl1,
           const uint32_t* __restrict__ w2tw,
           uint32_t* __restrict__ y2bw, float* __restrict__ y2hi,
           int base, int nend)
{
    extern __shared__ uint32_t smem[];
    const int tid  = threadIdx.x;
    const int wid  = tid >> 5;
    const int lane = tid & 31;
    const int wm   = wid & 1;
    const int wn   = wid >> 1;
    const int g    = lane >> 2;
    const int tg   = lane & 3;
    const int row0 = base + blockIdx.x * 128;

    const uint32_t sm_b = smem_u32(smem);

    float c[4][4][4];
#pragma unroll
    for (int mi = 0; mi < 4; mi++)
#pragma unroll
        for (int ni = 0; ni < 4; ni++)
#pragma unroll
            for (int j = 0; j < 4; j++) c[mi][ni][j] = 0.f;

    // -------- W2 tile load (own commit group, consumed in phase 2) --------
#pragma unroll
    for (int i = tid; i < 2048; i += 256) {            // 128 rows x 16 uint4
        int r = i >> 4, c4 = (i & 15) << 2;
        cp_async16(sm_b + (uint32_t)((W2S_OFF + r * 68 + c4) * 4),
                   w2tw + (size_t)r * 64 + c4, 16);
    }
    CP_COMMIT();

    // -------- phase 1: [mean|x] @ W1t, K=256 (8 chunks of 16 words) --------
    auto prefetch = [&](int ch, int stage) {
        const uint32_t* Aw = (ch < 4) ? meanw : xhw;
        int kkw = (ch & 3) * 16;
#pragma unroll
        for (int i = tid; i < 512; i += 256) {
            int r = i >> 2, g4 = (i & 3) << 2;
            int node = row0 + r;
            int ok = (node < nend);
            const uint32_t* gA = Aw + (size_t)(ok ? node : 0) * 64 + kkw + g4;
            cp_async16(sm_b + (uint32_t)((stage * P1_TILE + r * 20 + g4) * 4), gA, ok ? 16 : 0);
            const uint32_t* gW = w1tw + (size_t)r * 128 + ch * 16 + g4;
            cp_async16(sm_b + (uint32_t)(((2 + stage) * P1_TILE + r * 20 + g4) * 4), gW, 16);
        }
        CP_COMMIT();
    };

    prefetch(0, 0);

#pragma unroll 1
    for (int ch = 0; ch < 8; ++ch) {
        const int stage = ch & 1;
        if (ch + 1 < 8) {
            prefetch(ch + 1, stage ^ 1);
            CP_WAIT1();
        } else {
            CP_WAIT0();
        }
        __syncthreads();

        const uint32_t* Ab = smem + stage * P1_TILE;
        const uint32_t* Wb = smem + (2 + stage) * P1_TILE;

#pragma unroll
        for (int ks = 0; ks < 2; ++ks) {
            const int k0 = ks * 8;
            uint32_t a[4][4];
#pragma unroll
            for (int mi = 0; mi < 4; mi++) {
                int r0 = wm * 64 + mi * 16 + g;
                a[mi][0] = Ab[r0 * 20 + k0 + tg];
                a[mi][1] = Ab[(r0 + 8) * 20 + k0 + tg];
                a[mi][2] = Ab[r0 * 20 + k0 + tg + 4];
                a[mi][3] = Ab[(r0 + 8) * 20 + k0 + tg + 4];
            }
#pragma unroll
            for (int ni = 0; ni < 4; ni++) {
                int nb = wn * 32 + ni * 8 + g;
                uint32_t b[2];
                b[0] = Wb[nb * 20 + k0 + tg];
                b[1] = Wb[nb * 20 + k0 + tg + 4];
#pragma unroll
                for (int mi = 0; mi < 4; mi++)
                    mma_f16(c[mi][ni], a[mi], b);
            }
        }
        __syncthreads();
    }

    // -------- h = relu(c + bl1) -> SMEM (fp16 pairs) --------
#pragma unroll
    for (int mi = 0; mi < 4; mi++) {
#pragma unroll
        for (int half = 0; half < 2; half++) {
            int rl = wm * 64 + mi * 16 + g + half * 8;   // local row 0..127
#pragma unroll
            for (int ni = 0; ni < 4; ni++) {
                int col = wn * 32 + ni * 8 + tg * 2;
                float v0 = fmaxf(c[mi][ni][half * 2 + 0] + __ldg(&bl1[col]), 0.f);
                float v1 = fmaxf(c[mi][ni][half * 2 + 1] + __ldg(&bl1[col + 1]), 0.f);
                smem[HS_OFF + rl * 68 + (col >> 1)] = f2h2(v0, v1);
            }
        }
    }
    __syncthreads();

    // -------- phase 2: y2 = h @ W2t, K=128 --------
#pragma unroll
    for (int mi = 0; mi < 4; mi++)
#pragma unroll
        for (int ni = 0; ni < 4; ni++)
#pragma unroll
            for (int j = 0; j < 4; j++) c[mi][ni][j] = 0.f;

    const uint32_t* Hs  = smem + HS_OFF;
    const uint32_t* W2s = smem + W2S_OFF;
#pragma unroll
    for (int ks = 0; ks < 8; ++ks) {
        const int k0 = ks * 8;
        uint32_t a[4][4];
#pragma unroll
        for (int mi = 0; mi < 4; mi++) {
            int r0 = wm * 64 + mi * 16 + g;
            a[mi][0] = Hs[r0 * 68 + k0 + tg];
            a[mi][1] = Hs[(r0 + 8) * 68 + k0 + tg];
            a[mi][2] = Hs[r0 * 68 + k0 + tg + 4];
            a[mi][3] = Hs[(r0 + 8) * 68 + k0 + tg + 4];
        }
#pragma unroll
        for (int ni = 0; ni < 4; ni++) {
            int nb = wn * 32 + ni * 8 + g;
            uint32_t b[2];
            b[0] = W2s[nb * 68 + k0 + tg];
            b[1] = W2s[nb * 68 + k0 + tg + 4];
#pragma unroll
            for (int mi = 0; mi < 4; mi++)
                mma_f16(c[mi][ni], a[mi], b);
        }
    }

    // -------- epilogue --------
#pragma unroll
    for (int mi = 0; mi < 4; mi++) {
#pragma unroll
        for (int half = 0; half < 2; half++) {
            int row = row0 + wm * 64 + mi * 16 + g + half * 8;
            if (row < nend) {
#pragma unroll
                for (int ni = 0; ni < 4; ni++) {
                    int col = wn * 32 + ni * 8 + tg * 2;
                    float v0 = c[mi][ni][half * 2 + 0];
                    float v1 = c[mi][ni][half * 2 + 1];
                    if (col < 64) {
                        y2bw[(size_t)row * 32 + (col >> 1)] = f2h2(v0, v1);
                    } else {
                        *(float2*)(y2hi + (size_t)row * 64 + (col - 64)) =
                            make_float2(v0, v1);
                    }
                }
            }
        }
    }
}

// ---------------------------------------------------------------------------
extern "C" void kernel_launch(void* const* d_in, const int* in_sizes, int n_in,
                              void* d_out, int out_size) {
    const float* x   = (const float*)d_in[0];
    const void*  ei  = d_in[1];
    const float* Wl1 = (const float*)d_in[2];
    const float* bl1 = (const float*)d_in[3];
    const float* Wr1 = (const float*)d_in[4];
    const float* Wl2 = (const float*)d_in[5];
    const float* bl2 = (const float*)d_in[6];
    const float* Wr2 = (const float*)d_in[7];
    float* out = (float*)d_out;

    const int n  = in_sizes[0] / 128;   // 100000
    const int ne = in_sizes[1] / 2;     // 1600000

    uint32_t *meanw, *xhw, *y2bw, *w1tw, *w2tw;
    float *y2hi;
    int *cnt, *slot;
    cudaGetSymbolAddress((void**)&meanw,  g_meanw);
    cudaGetSymbolAddress((void**)&xhw,    g_xhw);
    cudaGetSymbolAddress((void**)&y2bw,   g_y2bw);
    cudaGetSymbolAddress((void**)&y2hi,   g_y2hi);
    cudaGetSymbolAddress((void**)&w1tw,   g_w1tw);
    cudaGetSymbolAddress((void**)&w2tw,   g_w2tw);
    cudaGetSymbolAddress((void**)&cnt,    g_cnt);
    cudaGetSymbolAddress((void**)&slot,   g_slot);

    const int SMEM_BYTES = FUSED_SMEM_WORDS * 4;   // 108 KB
    cudaFuncSetAttribute(fused_gemm,
                         cudaFuncAttributeMaxDynamicSharedMemorySize, SMEM_BYTES);

    const int n2    = ((n / 2 + 127) / 128) * 128;   // 0.5 split
    const int eblk2 = (ne / 2 + 255) / 256 + 1;
    const int gblkA = (n2 + 15) / 16;
    const int gblkB = (n - n2 + 15) / 16;
    const int gblkF = (n + 31) / 32;
    const int mblkA = n2 / 128;
    const int mblkB = (n - n2 + 127) / 128;
    const int n32   = n * 32;
    const int pitems = n32 + 128 * 128 + 128 * 64;
    const int pblk  = (pitems + 255) / 256;

    // Fork resources (host-side only; intentionally not destroyed — capture-
    // referenced objects must outlive the graph).
    cudaStream_t sB;
    cudaStreamCreateWithFlags(&sB, cudaStreamNonBlocking);
    cudaEvent_t ev0, evP, evGA, ev2A;
    cudaEventCreateWithFlags(&ev0,  cudaEventDisableTiming);
    cudaEventCreateWithFlags(&evP,  cudaEventDisableTiming);
    cudaEventCreateWithFlags(&evGA, cudaEventDisableTiming);
    cudaEventCreateWithFlags(&ev2A, cudaEventDisableTiming);

    // ---- fork S1 at capture root: prep runs parallel with adjacency build ----
    cudaEventRecord(ev0, 0);
    cudaStreamWaitEvent(sB, ev0, 0);
    prep_kernel<<<pblk, 256, 0, sB>>>(x, xhw, Wl1, Wr1, w1tw, Wl2, Wr2, w2tw, n32);
    cudaEventRecord(evP, sB);

    // ---- S0: zero cnt + detect, then single-pass slot fill ----
    zero_detect_kernel<<<(n + 255) / 256, 256>>>(cnt, (const int*)ei, n);
    fill_direct_kernel<<<eblk2, 256>>>(ei, cnt, slot, ne);

    // ---- S0: gather half A, then half B ----
    cudaStreamWaitEvent(0, evP, 0);
    gather_mean128_w<<<gblkA, 256>>>(xhw, cnt, slot, meanw, 0, n2);
    cudaEventRecord(evGA, 0);
    gather_mean128_w<<<gblkB, 256>>>(xhw, cnt, slot, meanw, n2, n);

    // ---- S1: fused GEMM for half A (overlaps gather_B) ----
    cudaStreamWaitEvent(sB, evGA, 0);
    fused_gemm<<<mblkA, 256, SMEM_BYTES, sB>>>(meanw, xhw, w1tw, bl1, w2tw,
                                               y2bw, y2hi, 0, n2);
    cudaEventRecord(ev2A, sB);

    // ---- S0: fused GEMM for half B ----
    fused_gemm<<<mblkB, 256, SMEM_BYTES>>>(meanw, xhw, w1tw, bl1, w2tw,
                                           y2bw, y2hi, n2, n);

    // ---- S0: join + final gather ----
    cudaStreamWaitEvent(0, ev2A, 0);
    gather_final64_w<<<gblkF, 256>>>(y2bw, y2hi, bl2, cnt, slot, out, n);
}